// round 1
// baseline (speedup 1.0000x reference)
#include <cuda_runtime.h>

// ---------------------------------------------------------------------------
// SparseAttention: qkv proj (tf32 mma) -> banded per-offset block attention
// (tf32 mma + fp32 softmax) -> output proj (tf32 mma).
// B=8, N=8192, C=512, heads=8 (dh=64), BLOCK=32 -> nb=256, WINDOW=64 blocks.
// Attention contracts over full C; only same in-block offset s attends.
// ---------------------------------------------------------------------------

#define DEVI __device__ __forceinline__

// Scratch: q/k/v in [bs=b*32+s][block j][c] layout; attn out token-major.
__device__ float g_q[33554432];
__device__ float g_k[33554432];
__device__ float g_v[33554432];
__device__ float g_attn[33554432];

DEVI unsigned f2tf(float f) {
    unsigned u;
    asm("cvt.rna.tf32.f32 %0, %1;" : "=r"(u) : "f"(f));
    return u;
}

// mma.sync m16n8k8 tf32, D += A*B (fp32 accum)
DEVI void mma8(float* d, const unsigned* a, const unsigned* b) {
    asm("mma.sync.aligned.m16n8k8.row.col.f32.tf32.tf32.f32 "
        "{%0,%1,%2,%3}, {%4,%5,%6,%7}, {%8,%9}, {%0,%1,%2,%3};"
        : "+f"(d[0]), "+f"(d[1]), "+f"(d[2]), "+f"(d[3])
        : "r"(a[0]), "r"(a[1]), "r"(a[2]), "r"(a[3]), "r"(b[0]), "r"(b[1]));
}

// ---------------------------------------------------------------------------
// Generic GEMM: A[65536 x 512] (fp32, row-major) * B[512 x N] + bias.
// EPI==0: qkv epilogue (head-split permute into g_q/g_k/g_v)
// EPI==1: plain row-major store to out.
// CTA tile 128x128, ktile 32, 8 warps (warp tile 32x64), double-buffered smem.
// ---------------------------------------------------------------------------
template <int N, int EPI>
__global__ void __launch_bounds__(256) gemm_tf32(
    const float* __restrict__ A, const float* __restrict__ B,
    const float* __restrict__ bias, float* __restrict__ out)
{
    extern __shared__ unsigned char gsm[];
    unsigned* As = (unsigned*)gsm;                     // [2][128][36]
    unsigned* Bs = (unsigned*)(gsm + 2 * 128 * 36 * 4); // [2][32][132]

    const int tid = threadIdx.x, lane = tid & 31, wid = tid >> 5;
    const int wm = wid & 3, wn = wid >> 2;   // 4 x 2 warp grid (M x N)
    const int mt = blockIdx.y, nt = blockIdx.x;

    const float* Ag = A + (size_t)mt * 128 * 512;
    const float* Bg = B + nt * 128;

    float4 ra[4], rb[4];

    auto ldg = [&](int kt) {
        const int k0 = kt * 32;
#pragma unroll
        for (int i = 0; i < 4; i++) {
            int lin = tid + i * 256;
            ra[i] = *(const float4*)(Ag + (lin >> 3) * 512 + k0 + (lin & 7) * 4);
            rb[i] = *(const float4*)(Bg + (size_t)(k0 + (lin >> 5)) * N + (lin & 31) * 4);
        }
    };
    auto sts = [&](int buf) {
#pragma unroll
        for (int i = 0; i < 4; i++) {
            int lin = tid + i * 256;
            uint4 ta = make_uint4(f2tf(ra[i].x), f2tf(ra[i].y), f2tf(ra[i].z), f2tf(ra[i].w));
            *(uint4*)&As[buf * 4608 + (lin >> 3) * 36 + (lin & 7) * 4] = ta;
            uint4 tb = make_uint4(f2tf(rb[i].x), f2tf(rb[i].y), f2tf(rb[i].z), f2tf(rb[i].w));
            *(uint4*)&Bs[buf * 4224 + (lin >> 5) * 132 + (lin & 31) * 4] = tb;
        }
    };

    float acc[2][8][4];
#pragma unroll
    for (int mf = 0; mf < 2; mf++)
#pragma unroll
        for (int nf = 0; nf < 8; nf++)
#pragma unroll
            for (int r = 0; r < 4; r++) acc[mf][nf][r] = 0.f;

    ldg(0);
    sts(0);
    __syncthreads();

    for (int kt = 0; kt < 16; kt++) {
        if (kt < 15) ldg(kt + 1);
        const int buf = kt & 1;
#pragma unroll
        for (int kk = 0; kk < 4; kk++) {
            const int k = kk * 8 + (lane & 3);
            unsigned af[2][4], bf[8][2];
#pragma unroll
            for (int mf = 0; mf < 2; mf++) {
                int row = wm * 32 + mf * 16 + (lane >> 2);
                const unsigned* p = &As[buf * 4608 + row * 36 + k];
                af[mf][0] = p[0];          // (g,   t)
                af[mf][1] = p[8 * 36];     // (g+8, t)
                af[mf][2] = p[4];          // (g,   t+4)
                af[mf][3] = p[8 * 36 + 4]; // (g+8, t+4)
            }
#pragma unroll
            for (int nf = 0; nf < 8; nf++) {
                int col = wn * 64 + nf * 8 + (lane >> 2);
                const unsigned* p = &Bs[buf * 4224 + k * 132 + col];
                bf[nf][0] = p[0];
                bf[nf][1] = p[4 * 132];
            }
#pragma unroll
            for (int mf = 0; mf < 2; mf++)
#pragma unroll
                for (int nf = 0; nf < 8; nf++)
                    mma8(acc[mf][nf], af[mf], bf[nf]);
        }
        if (kt < 15) sts(buf ^ 1);
        __syncthreads();
    }

    // epilogue
#pragma unroll
    for (int mf = 0; mf < 2; mf++)
#pragma unroll
        for (int nf = 0; nf < 8; nf++)
#pragma unroll
            for (int r = 0; r < 4; r++) {
                int row = mt * 128 + wm * 32 + mf * 16 + (lane >> 2) + ((r & 2) ? 8 : 0);
                int cc = nt * 128 + wn * 64 + nf * 8 + (lane & 3) * 2 + (r & 1);
                float v = acc[mf][nf][r] + bias[cc];
                if (EPI == 0) {
                    // row -> (b, n); n -> (block j, offset s); cc -> (head, kind, d)
                    int b = row >> 13, n = row & 8191;
                    int j = n >> 5, s = n & 31;
                    int hh = cc / 192, rr = cc - hh * 192;
                    int kind = rr >> 6, d = rr & 63;
                    int c = hh * 64 + d;
                    int dst = ((b * 32 + s) * 256 + j) * 512 + c;
                    float* dp = (kind == 0) ? g_q : (kind == 1) ? g_k : g_v;
                    dp[dst] = v;
                } else {
                    out[(size_t)row * 512 + cc] = v;
                }
            }
}

// ---------------------------------------------------------------------------
// Banded attention per (bs = b*32+s, 64-query tile). W = band width (128/192).
// Phase1: S = Q K^T (tf32 mma), scale+mask, fp32 softmax in smem,
// Phase2: O = P V (tf32 mma), written token-major into g_attn.
// ---------------------------------------------------------------------------
template <int W>
__global__ void __launch_bounds__(256) attn_kernel()
{
    constexpr int NF1 = W / 32;   // phase1 n-frags per warp; also #ktiles phase2
    constexpr int SST = W + 4;    // S row stride (floats)

    extern __shared__ unsigned char smraw[];
    float* Ss = (float*)smraw;                       // [64][SST]
    unsigned* Sp = (unsigned*)smraw;                 // tf32 alias of P
    unsigned* Qs = (unsigned*)(smraw + 64 * SST * 4); // [2][64][36]
    unsigned* Ks = Qs + 2 * 64 * 36;                 // [2][W][36]
    unsigned* Vs = Qs;                               // phase2: [2][32][260]

    const int tid = threadIdx.x, lane = tid & 31, wid = tid >> 5;
    const int bs = blockIdx.y;
    const int qt = (W == 128) ? (blockIdx.x ? 3 : 0) : (1 + blockIdx.x);
    const int i0 = qt * 64;
    const int jlo = (i0 >= 64) ? (i0 - 64) : 0;

    const float* Qg = g_q + (size_t)(bs * 256 + i0) * 512;
    const float* Kg = g_k + (size_t)(bs * 256 + jlo) * 512;
    const float* Vg = g_v + (size_t)(bs * 256 + jlo) * 512;

    const int wm = wid & 1, wn = wid >> 1;  // 2 x 4 warp grid

    // ---------------- phase 1: S = Q K^T ----------------
    float4 rq[2], rk[NF1];
    auto ldg1 = [&](int kt) {
        const int k0 = kt * 32;
#pragma unroll
        for (int i = 0; i < 2; i++) {
            int lin = tid + i * 256;
            rq[i] = *(const float4*)(Qg + (lin >> 3) * 512 + k0 + (lin & 7) * 4);
        }
#pragma unroll
        for (int i = 0; i < NF1; i++) {
            int lin = tid + i * 256;
            rk[i] = *(const float4*)(Kg + (lin >> 3) * 512 + k0 + (lin & 7) * 4);
        }
    };
    auto sts1 = [&](int buf) {
#pragma unroll
        for (int i = 0; i < 2; i++) {
            int lin = tid + i * 256;
            uint4 t = make_uint4(f2tf(rq[i].x), f2tf(rq[i].y), f2tf(rq[i].z), f2tf(rq[i].w));
            *(uint4*)&Qs[buf * 2304 + (lin >> 3) * 36 + (lin & 7) * 4] = t;
        }
#pragma unroll
        for (int i = 0; i < NF1; i++) {
            int lin = tid + i * 256;
            uint4 t = make_uint4(f2tf(rk[i].x), f2tf(rk[i].y), f2tf(rk[i].z), f2tf(rk[i].w));
            *(uint4*)&Ks[buf * (W * 36) + (lin >> 3) * 36 + (lin & 7) * 4] = t;
        }
    };

    float acc[2][NF1][4];
#pragma unroll
    for (int mf = 0; mf < 2; mf++)
#pragma unroll
        for (int nf = 0; nf < NF1; nf++)
#pragma unroll
            for (int r = 0; r < 4; r++) acc[mf][nf][r] = 0.f;

    ldg1(0);
    sts1(0);
    __syncthreads();

    for (int kt = 0; kt < 16; kt++) {
        if (kt < 15) ldg1(kt + 1);
        const int buf = kt & 1;
#pragma unroll
        for (int kk = 0; kk < 4; kk++) {
            const int k = kk * 8 + (lane & 3);
            unsigned af[2][4], bf[NF1][2];
#pragma unroll
            for (int mf = 0; mf < 2; mf++) {
                int row = wm * 32 + mf * 16 + (lane >> 2);
                const unsigned* p = &Qs[buf * 2304 + row * 36 + k];
                af[mf][0] = p[0];
                af[mf][1] = p[8 * 36];
                af[mf][2] = p[4];
                af[mf][3] = p[8 * 36 + 4];
            }
#pragma unroll
            for (int nf = 0; nf < NF1; nf++) {
                int col = wn * (W / 4) + nf * 8 + (lane >> 2);
                const unsigned* p = &Ks[buf * (W * 36) + col * 36 + k];
                bf[nf][0] = p[0];
                bf[nf][1] = p[4];
            }
#pragma unroll
            for (int mf = 0; mf < 2; mf++)
#pragma unroll
                for (int nf = 0; nf < NF1; nf++)
                    mma8(acc[mf][nf], af[mf], bf[nf]);
        }
        if (kt < 15) sts1(buf ^ 1);
        __syncthreads();
    }

    // scale + band mask + store S to smem
#pragma unroll
    for (int mf = 0; mf < 2; mf++)
#pragma unroll
        for (int nf = 0; nf < NF1; nf++)
#pragma unroll
            for (int r = 0; r < 4; r++) {
                int row = wm * 32 + mf * 16 + (lane >> 2) + ((r & 2) ? 8 : 0);
                int jl = wn * (W / 4) + nf * 8 + (lane & 3) * 2 + (r & 1);
                int i = i0 + row, j = jlo + jl;
                float v = acc[mf][nf][r] * 0.125f;  // dh^-0.5, dh=64
                if (j < i - 64 || j > i + 64) v = -3.0e38f;
                Ss[row * SST + jl] = v;
            }
    __syncthreads();

    // fp32 softmax: 4 threads per row
    {
        const int row = tid >> 2, part = tid & 3;
        float* rp = Ss + row * SST;
        float mx = -3.4e38f;
        for (int jl = part; jl < W; jl += 4) mx = fmaxf(mx, rp[jl]);
        mx = fmaxf(mx, __shfl_xor_sync(0xffffffffu, mx, 1));
        mx = fmaxf(mx, __shfl_xor_sync(0xffffffffu, mx, 2));
        float sm = 0.f;
        for (int jl = part; jl < W; jl += 4) {
            float e = __expf(rp[jl] - mx);
            rp[jl] = e;
            sm += e;
        }
        sm += __shfl_xor_sync(0xffffffffu, sm, 1);
        sm += __shfl_xor_sync(0xffffffffu, sm, 2);
        float inv = 1.0f / sm;
        unsigned* up = Sp + row * SST;
        for (int jl = part; jl < W; jl += 4) up[jl] = f2tf(rp[jl] * inv);
    }
    __syncthreads();

    // ---------------- phase 2: O = P V ----------------
    const int b = bs >> 5, s = bs & 31;
    for (int half = 0; half < 2; half++) {
        float acc2[2][8][4];
#pragma unroll
        for (int mf = 0; mf < 2; mf++)
#pragma unroll
            for (int nf = 0; nf < 8; nf++)
#pragma unroll
                for (int r = 0; r < 4; r++) acc2[mf][nf][r] = 0.f;

        float4 rv[8];
        auto ldg2 = [&](int kt) {
#pragma unroll
            for (int i = 0; i < 8; i++) {
                int lin = tid + i * 256;
                rv[i] = *(const float4*)(Vg + (size_t)(kt * 32 + (lin >> 6)) * 512 +
                                          half * 256 + (lin & 63) * 4);
            }
        };
        auto sts2 = [&](int buf) {
#pragma unroll
            for (int i = 0; i < 8; i++) {
                int lin = tid + i * 256;
                uint4 t = make_uint4(f2tf(rv[i].x), f2tf(rv[i].y), f2tf(rv[i].z), f2tf(rv[i].w));
                *(uint4*)&Vs[buf * 8320 + (lin >> 6) * 260 + (lin & 63) * 4] = t;
            }
        };

        ldg2(0);
        sts2(0);
        __syncthreads();

        for (int kt = 0; kt < NF1; kt++) {
            if (kt < NF1 - 1) ldg2(kt + 1);
            const int buf = kt & 1;
#pragma unroll
            for (int kk = 0; kk < 4; kk++) {
                const int kA = kt * 32 + kk * 8 + (lane & 3);
                const int kl = kk * 8 + (lane & 3);
                unsigned af[2][4], bf[8][2];
#pragma unroll
                for (int mf = 0; mf < 2; mf++) {
                    int row = wm * 32 + mf * 16 + (lane >> 2);
                    af[mf][0] = Sp[row * SST + kA];
                    af[mf][1] = Sp[(row + 8) * SST + kA];
                    af[mf][2] = Sp[row * SST + kA + 4];
                    af[mf][3] = Sp[(row + 8) * SST + kA + 4];
                }
#pragma unroll
                for (int nf = 0; nf < 8; nf++) {
                    int col = wn * 64 + nf * 8 + (lane >> 2);
                    bf[nf][0] = Vs[buf * 8320 + kl * 260 + col];
                    bf[nf][1] = Vs[buf * 8320 + (kl + 4) * 260 + col];
                }
#pragma unroll
                for (int mf = 0; mf < 2; mf++)
#pragma unroll
                    for (int nf = 0; nf < 8; nf++)
                        mma8(acc2[mf][nf], af[mf], bf[nf]);
            }
            if (kt < NF1 - 1) sts2(buf ^ 1);
            __syncthreads();
        }

#pragma unroll
        for (int mf = 0; mf < 2; mf++)
#pragma unroll
            for (int nf = 0; nf < 8; nf++)
#pragma unroll
                for (int r = 0; r < 4; r++) {
                    int row = wm * 32 + mf * 16 + (lane >> 2) + ((r & 2) ? 8 : 0);
                    int c = half * 256 + wn * 64 + nf * 8 + (lane & 3) * 2 + (r & 1);
                    int t = b * 8192 + (i0 + row) * 32 + s;
                    g_attn[(size_t)t * 512 + c] = acc2[mf][nf][r];
                }
        __syncthreads();
    }
}

// ---------------------------------------------------------------------------
extern "C" void kernel_launch(void* const* d_in, const int* in_sizes, int n_in,
                              void* d_out, int out_size)
{
    const float* x  = (const float*)d_in[0];
    const float* Wq = (const float*)d_in[1];
    const float* bq = (const float*)d_in[2];
    const float* Wp = (const float*)d_in[3];
    const float* bp = (const float*)d_in[4];
    float* out = (float*)d_out;

    const int smG = 2 * 128 * 36 * 4 + 2 * 32 * 132 * 4;          // 70656
    const int smA128 = 64 * 132 * 4 + 2 * 32 * 260 * 4;            // 100352
    const int smA192 = 64 * 196 * 4 + (2 * 64 * 36 + 2 * 192 * 36) * 4; // 123904

    cudaFuncSetAttribute(gemm_tf32<1536, 0>, cudaFuncAttributeMaxDynamicSharedMemorySize, smG);
    cudaFuncSetAttribute(gemm_tf32<512, 1>, cudaFuncAttributeMaxDynamicSharedMemorySize, smG);
    cudaFuncSetAttribute(attn_kernel<128>, cudaFuncAttributeMaxDynamicSharedMemorySize, smA128);
    cudaFuncSetAttribute(attn_kernel<192>, cudaFuncAttributeMaxDynamicSharedMemorySize, smA192);

    // 1) QKV projection + head-split permute into g_q/g_k/g_v
    gemm_tf32<1536, 0><<<dim3(12, 512), 256, smG>>>(x, Wq, bq, nullptr);

    // 2) banded attention (band width 128 tiles: qt 0,3; width 192: qt 1,2)
    attn_kernel<128><<<dim3(2, 256), 256, smA128>>>();
    attn_kernel<192><<<dim3(2, 256), 256, smA192>>>();

    // 3) output projection
    void* pattn = nullptr;
    cudaGetSymbolAddress(&pattn, g_attn);
    gemm_tf32<512, 1><<<dim3(4, 512), 256, smG>>>((const float*)pattn, Wp, bp, out);
}

// round 3
// speedup vs baseline: 1.3023x; 1.3023x over previous
#include <cuda_runtime.h>
#include <cstdint>

#define DEVI __device__ __forceinline__

// ---------------------------------------------------------------------------
// Scratch (device globals; no allocation allowed)
// ---------------------------------------------------------------------------
__device__ float g_q[33554432];     // [bs=b*32+s][block j][c]  (canonical)
__device__ float g_k[33554432];
__device__ float g_v[33554432];
__device__ float g_attn[33554432];  // attention output, PACKED mma-fragment order
__device__ float g_xr[33554432];    // x, PACKED mma-fragment order, tf32-rounded
__device__ float g_wq[786432];      // W_qkv^T packed fragments (B side)
__device__ float g_wp[262144];      // W_proj^T packed fragments (B side)

DEVI unsigned f2tf(float f) {
    unsigned u;
    asm("cvt.rna.tf32.f32 %0, %1;" : "=r"(u) : "f"(f));
    return u;
}

DEVI uint32_t smem_u32(const void* p) {
    uint32_t a;
    asm("{ .reg .u64 t; cvta.to.shared.u64 t, %1; cvt.u32.u64 %0, t; }" : "=r"(a) : "l"(p));
    return a;
}

DEVI uint4 lds128(uint32_t a) {
    uint4 v;
    asm volatile("ld.shared.v4.u32 {%0,%1,%2,%3}, [%4];"
                 : "=r"(v.x), "=r"(v.y), "=r"(v.z), "=r"(v.w) : "r"(a));
    return v;
}

DEVI void cp16(uint32_t s, const void* g) {
    asm volatile("cp.async.cg.shared.global [%0], [%1], 16;" :: "r"(s), "l"(g));
}
DEVI void cp_commit() { asm volatile("cp.async.commit_group;"); }
template <int N> DEVI void cp_wait() { asm volatile("cp.async.wait_group %0;" :: "n"(N)); }

// mma.sync m16n8k8 tf32, D += A*B (fp32 accum)
DEVI void mma8(float* d, const unsigned* a, unsigned b0, unsigned b1) {
    asm("mma.sync.aligned.m16n8k8.row.col.f32.tf32.tf32.f32 "
        "{%0,%1,%2,%3}, {%4,%5,%6,%7}, {%8,%9}, {%0,%1,%2,%3};"
        : "+f"(d[0]), "+f"(d[1]), "+f"(d[2]), "+f"(d[3])
        : "r"(a[0]), "r"(a[1]), "r"(a[2]), "r"(a[3]), "r"(b0), "r"(b1));
}

// ---------------------------------------------------------------------------
// Packed fragment layouts (per 128x32 k-tile = 1024 uint4 = 16KB):
// A: u = wm*256 + mf*128 + kk*32 + l ; elems {(r,k),(r+8,k),(r,k+4),(r+8,k+4)}
//    r = 128*mt + wm*32 + mf*16 + (l>>2),  k = 32*kt + kk*8 + (l&3)
// B: u = wn*512 + nfp*128 + kk*32 + l ; elems {(c,k),(c,k+4),(c+8,k),(c+8,k+4)}
//    c = 128*nt + wn*64 + nfp*16 + (l>>2), k as above   (c = output column)
// ---------------------------------------------------------------------------

// x[65536,512] -> g_xr packed (rounded). One uint4 per thread.
__global__ void pack_x(const float* __restrict__ x, uint4* __restrict__ o) {
    int u = blockIdx.x * 256 + threadIdx.x;
    int l = u & 31, kk = (u >> 5) & 3, mf = (u >> 7) & 1, wm = (u >> 8) & 3;
    int kt = (u >> 10) & 15, mt = u >> 14;
    int r = mt * 128 + wm * 32 + mf * 16 + (l >> 2);
    int k = kt * 32 + kk * 8 + (l & 3);
    const float* p = x + (size_t)r * 512 + k;
    uint4 v;
    v.x = f2tf(p[0]);
    v.y = f2tf(p[8 * 512]);
    v.z = f2tf(p[4]);
    v.w = f2tf(p[8 * 512 + 4]);
    o[u] = v;
}

// W[512, NTOT] (k-major, as given) -> packed B fragments (rounded).
template <int NTOT>
__global__ void pack_w(const float* __restrict__ W, uint4* __restrict__ o) {
    int u = blockIdx.x * 256 + threadIdx.x;
    int l = u & 31, kk = (u >> 5) & 3, nfp = (u >> 7) & 3, wn = (u >> 9) & 1;
    int kt = (u >> 10) & 15, nt = u >> 14;
    int c = nt * 128 + wn * 64 + nfp * 16 + (l >> 2);
    int k = kt * 32 + kk * 8 + (l & 3);
    uint4 v;
    v.x = f2tf(W[(size_t)k * NTOT + c]);
    v.y = f2tf(W[(size_t)(k + 4) * NTOT + c]);
    v.z = f2tf(W[(size_t)k * NTOT + c + 8]);
    v.w = f2tf(W[(size_t)(k + 4) * NTOT + c + 8]);
    o[u] = v;
}

// Scatter one value into packed-A layout (used by attention epilogue).
DEVI void store_attn_packed(int m, int c, float val) {
    int mt = m >> 7, rr = m & 127;
    int wm = rr >> 5, mf = (rr >> 4) & 1, r8 = rr & 15;
    int e0 = r8 >> 3, lhi = r8 & 7;
    int kt = c >> 5, c5 = c & 31, kk = c5 >> 3, cm = c5 & 7;
    int e1 = cm >> 2, llo = cm & 3;
    size_t u = ((size_t)(mt * 16 + kt)) * 1024 + wm * 256 + mf * 128 + kk * 32 + lhi * 4 + llo;
    g_attn[u * 4 + e1 * 2 + e0] = val;
}

// ---------------------------------------------------------------------------
// Fragment-packed tf32 GEMM via mma.sync.
// A packed [Mtiles][16][1024] uint4, B packed [Ntiles][16][1024] uint4.
// CTA 128x128, 8 warps (4x2), 3-stage cp.async.
// EPI==0: qkv head-split scatter to g_q/g_k/g_v.  EPI==1: row-major out.
// ---------------------------------------------------------------------------
template <int EPI>
__global__ void __launch_bounds__(256, 2) tc_gemm(
    const uint4* __restrict__ Apk, const uint4* __restrict__ Bpk,
    const float* __restrict__ bias, float* __restrict__ out)
{
    extern __shared__ unsigned char sm[];
    const uint32_t smb = smem_u32(sm);
    const int tid = threadIdx.x, lane = tid & 31, wid = tid >> 5;
    const int wm = wid & 3, wn = wid >> 2;
    const int nt = blockIdx.x, mt = blockIdx.y;

    const uint4* Ag = Apk + (size_t)mt * 16384 + tid;   // 16 ktiles * 1024
    const uint4* Bg = Bpk + (size_t)nt * 16384 + tid;

    auto load_tile = [&](int kt, int s) {
        const uint32_t dst = smb + s * 32768 + tid * 16;
        const uint4* sa = Ag + kt * 1024;
        const uint4* sb = Bg + kt * 1024;
#pragma unroll
        for (int i = 0; i < 4; i++) cp16(dst + i * 4096, sa + i * 256);
#pragma unroll
        for (int i = 0; i < 4; i++) cp16(dst + 16384 + i * 4096, sb + i * 256);
        cp_commit();
    };

    float acc[2][8][4];
#pragma unroll
    for (int mf = 0; mf < 2; mf++)
#pragma unroll
        for (int nf = 0; nf < 8; nf++)
#pragma unroll
            for (int r = 0; r < 4; r++) acc[mf][nf][r] = 0.f;

    load_tile(0, 0);
    load_tile(1, 1);

    for (int kt = 0; kt < 16; kt++) {
        if (kt < 15) cp_wait<1>(); else cp_wait<0>();
        __syncthreads();
        if (kt + 2 < 16) load_tile(kt + 2, (kt + 2) % 3);

        const uint32_t sbase = smb + (kt % 3) * 32768;
        const uint32_t aB = sbase + wm * 4096 + lane * 16;
        const uint32_t bB = sbase + 16384 + wn * 8192 + lane * 16;
#pragma unroll
        for (int kk = 0; kk < 4; kk++) {
            uint4 a0 = lds128(aB + kk * 512);
            uint4 a1 = lds128(aB + 2048 + kk * 512);
            uint4 b0 = lds128(bB + kk * 512);
            uint4 b1 = lds128(bB + 2048 + kk * 512);
            uint4 b2 = lds128(bB + 4096 + kk * 512);
            uint4 b3 = lds128(bB + 6144 + kk * 512);
            unsigned af0[4] = {a0.x, a0.y, a0.z, a0.w};
            unsigned af1[4] = {a1.x, a1.y, a1.z, a1.w};
            mma8(acc[0][0], af0, b0.x, b0.y);
            mma8(acc[0][1], af0, b0.z, b0.w);
            mma8(acc[0][2], af0, b1.x, b1.y);
            mma8(acc[0][3], af0, b1.z, b1.w);
            mma8(acc[0][4], af0, b2.x, b2.y);
            mma8(acc[0][5], af0, b2.z, b2.w);
            mma8(acc[0][6], af0, b3.x, b3.y);
            mma8(acc[0][7], af0, b3.z, b3.w);
            mma8(acc[1][0], af1, b0.x, b0.y);
            mma8(acc[1][1], af1, b0.z, b0.w);
            mma8(acc[1][2], af1, b1.x, b1.y);
            mma8(acc[1][3], af1, b1.z, b1.w);
            mma8(acc[1][4], af1, b2.x, b2.y);
            mma8(acc[1][5], af1, b2.z, b2.w);
            mma8(acc[1][6], af1, b3.x, b3.y);
            mma8(acc[1][7], af1, b3.z, b3.w);
        }
    }

    // epilogue (same D-fragment mapping as before)
#pragma unroll
    for (int mf = 0; mf < 2; mf++)
#pragma unroll
        for (int nf = 0; nf < 8; nf++)
#pragma unroll
            for (int r = 0; r < 4; r++) {
                int row = mt * 128 + wm * 32 + mf * 16 + (lane >> 2) + ((r & 2) ? 8 : 0);
                int cc = nt * 128 + wn * 64 + nf * 8 + (lane & 3) * 2 + (r & 1);
                float v = acc[mf][nf][r] + bias[cc];
                if (EPI == 0) {
                    int b = row >> 13, n = row & 8191;
                    int j = n >> 5, s = n & 31;
                    int hh = cc / 192, rr = cc - hh * 192;
                    int kind = rr >> 6, d = rr & 63;
                    int c = hh * 64 + d;
                    int dst = ((b * 32 + s) * 256 + j) * 512 + c;
                    float* dp = (kind == 0) ? g_q : (kind == 1) ? g_k : g_v;
                    dp[dst] = v;
                } else {
                    out[(size_t)row * 512 + cc] = v;
                }
            }
}

// ---------------------------------------------------------------------------
// Banded attention (R1-proven). Epilogue now writes packed+rounded g_attn.
// ---------------------------------------------------------------------------
DEVI void mma8a(float* d, const unsigned* a, const unsigned* b) {
    asm("mma.sync.aligned.m16n8k8.row.col.f32.tf32.tf32.f32 "
        "{%0,%1,%2,%3}, {%4,%5,%6,%7}, {%8,%9}, {%0,%1,%2,%3};"
        : "+f"(d[0]), "+f"(d[1]), "+f"(d[2]), "+f"(d[3])
        : "r"(a[0]), "r"(a[1]), "r"(a[2]), "r"(a[3]), "r"(b[0]), "r"(b[1]));
}

template <int W>
__global__ void __launch_bounds__(256) attn_kernel()
{
    constexpr int NF1 = W / 32;
    constexpr int SST = W + 4;

    extern __shared__ unsigned char smraw[];
    float* Ss = (float*)smraw;
    unsigned* Sp = (unsigned*)smraw;
    unsigned* Qs = (unsigned*)(smraw + 64 * SST * 4);
    unsigned* Ks = Qs + 2 * 64 * 36;
    unsigned* Vs = Qs;

    const int tid = threadIdx.x, lane = tid & 31, wid = tid >> 5;
    const int bs = blockIdx.y;
    const int qt = (W == 128) ? (blockIdx.x ? 3 : 0) : (1 + blockIdx.x);
    const int i0 = qt * 64;
    const int jlo = (i0 >= 64) ? (i0 - 64) : 0;

    const float* Qg = g_q + (size_t)(bs * 256 + i0) * 512;
    const float* Kg = g_k + (size_t)(bs * 256 + jlo) * 512;
    const float* Vg = g_v + (size_t)(bs * 256 + jlo) * 512;

    const int wm = wid & 1, wn = wid >> 1;

    float4 rq[2], rk[NF1];
    auto ldg1 = [&](int kt) {
        const int k0 = kt * 32;
#pragma unroll
        for (int i = 0; i < 2; i++) {
            int lin = tid + i * 256;
            rq[i] = *(const float4*)(Qg + (lin >> 3) * 512 + k0 + (lin & 7) * 4);
        }
#pragma unroll
        for (int i = 0; i < NF1; i++) {
            int lin = tid + i * 256;
            rk[i] = *(const float4*)(Kg + (lin >> 3) * 512 + k0 + (lin & 7) * 4);
        }
    };
    auto sts1 = [&](int buf) {
#pragma unroll
        for (int i = 0; i < 2; i++) {
            int lin = tid + i * 256;
            uint4 t = make_uint4(f2tf(rq[i].x), f2tf(rq[i].y), f2tf(rq[i].z), f2tf(rq[i].w));
            *(uint4*)&Qs[buf * 2304 + (lin >> 3) * 36 + (lin & 7) * 4] = t;
        }
#pragma unroll
        for (int i = 0; i < NF1; i++) {
            int lin = tid + i * 256;
            uint4 t = make_uint4(f2tf(rk[i].x), f2tf(rk[i].y), f2tf(rk[i].z), f2tf(rk[i].w));
            *(uint4*)&Ks[buf * (W * 36) + (lin >> 3) * 36 + (lin & 7) * 4] = t;
        }
    };

    float acc[2][NF1][4];
#pragma unroll
    for (int mf = 0; mf < 2; mf++)
#pragma unroll
        for (int nf = 0; nf < NF1; nf++)
#pragma unroll
            for (int r = 0; r < 4; r++) acc[mf][nf][r] = 0.f;

    ldg1(0);
    sts1(0);
    __syncthreads();

    for (int kt = 0; kt < 16; kt++) {
        if (kt < 15) ldg1(kt + 1);
        const int buf = kt & 1;
#pragma unroll
        for (int kk = 0; kk < 4; kk++) {
            const int k = kk * 8 + (lane & 3);
            unsigned af[2][4], bf[NF1][2];
#pragma unroll
            for (int mf = 0; mf < 2; mf++) {
                int row = wm * 32 + mf * 16 + (lane >> 2);
                const unsigned* p = &Qs[buf * 2304 + row * 36 + k];
                af[mf][0] = p[0];
                af[mf][1] = p[8 * 36];
                af[mf][2] = p[4];
                af[mf][3] = p[8 * 36 + 4];
            }
#pragma unroll
            for (int nf = 0; nf < NF1; nf++) {
                int col = wn * (W / 4) + nf * 8 + (lane >> 2);
                const unsigned* p = &Ks[buf * (W * 36) + col * 36 + k];
                bf[nf][0] = p[0];
                bf[nf][1] = p[4];
            }
#pragma unroll
            for (int mf = 0; mf < 2; mf++)
#pragma unroll
                for (int nf = 0; nf < NF1; nf++)
                    mma8a(acc[mf][nf], af[mf], bf[nf]);
        }
        if (kt < 15) sts1(buf ^ 1);
        __syncthreads();
    }

#pragma unroll
    for (int mf = 0; mf < 2; mf++)
#pragma unroll
        for (int nf = 0; nf < NF1; nf++)
#pragma unroll
            for (int r = 0; r < 4; r++) {
                int row = wm * 32 + mf * 16 + (lane >> 2) + ((r & 2) ? 8 : 0);
                int jl = wn * (W / 4) + nf * 8 + (lane & 3) * 2 + (r & 1);
                int i = i0 + row, j = jlo + jl;
                float v = acc[mf][nf][r] * 0.125f;
                if (j < i - 64 || j > i + 64) v = -3.0e38f;
                Ss[row * SST + jl] = v;
            }
    __syncthreads();

    {
        const int row = tid >> 2, part = tid & 3;
        float* rp = Ss + row * SST;
        float mx = -3.4e38f;
        for (int jl = part; jl < W; jl += 4) mx = fmaxf(mx, rp[jl]);
        mx = fmaxf(mx, __shfl_xor_sync(0xffffffffu, mx, 1));
        mx = fmaxf(mx, __shfl_xor_sync(0xffffffffu, mx, 2));
        float sm = 0.f;
        for (int jl = part; jl < W; jl += 4) {
            float e = __expf(rp[jl] - mx);
            rp[jl] = e;
            sm += e;
        }
        sm += __shfl_xor_sync(0xffffffffu, sm, 1);
        sm += __shfl_xor_sync(0xffffffffu, sm, 2);
        float inv = 1.0f / sm;
        unsigned* up = Sp + row * SST;
        for (int jl = part; jl < W; jl += 4) up[jl] = f2tf(rp[jl] * inv);
    }
    __syncthreads();

    const int b = bs >> 5, s = bs & 31;
    for (int half = 0; half < 2; half++) {
        float acc2[2][8][4];
#pragma unroll
        for (int mf = 0; mf < 2; mf++)
#pragma unroll
            for (int nf = 0; nf < 8; nf++)
#pragma unroll
                for (int r = 0; r < 4; r++) acc2[mf][nf][r] = 0.f;

        float4 rv[8];
        auto ldg2 = [&](int kt) {
#pragma unroll
            for (int i = 0; i < 8; i++) {
                int lin = tid + i * 256;
                rv[i] = *(const float4*)(Vg + (size_t)(kt * 32 + (lin >> 6)) * 512 +
                                          half * 256 + (lin & 63) * 4);
            }
        };
        auto sts2 = [&](int buf) {
#pragma unroll
            for (int i = 0; i < 8; i++) {
                int lin = tid + i * 256;
                uint4 t = make_uint4(f2tf(rv[i].x), f2tf(rv[i].y), f2tf(rv[i].z), f2tf(rv[i].w));
                *(uint4*)&Vs[buf * 8320 + (lin >> 6) * 260 + (lin & 63) * 4] = t;
            }
        };

        ldg2(0);
        sts2(0);
        __syncthreads();

        for (int kt = 0; kt < NF1; kt++) {
            if (kt < NF1 - 1) ldg2(kt + 1);
            const int buf = kt & 1;
#pragma unroll
            for (int kk = 0; kk < 4; kk++) {
                const int kA = kt * 32 + kk * 8 + (lane & 3);
                const int kl = kk * 8 + (lane & 3);
                unsigned af[2][4], bf[8][2];
#pragma unroll
                for (int mf = 0; mf < 2; mf++) {
                    int row = wm * 32 + mf * 16 + (lane >> 2);
                    af[mf][0] = Sp[row * SST + kA];
                    af[mf][1] = Sp[(row + 8) * SST + kA];
                    af[mf][2] = Sp[row * SST + kA + 4];
                    af[mf][3] = Sp[(row + 8) * SST + kA + 4];
                }
#pragma unroll
                for (int nf = 0; nf < 8; nf++) {
                    int col = wn * 64 + nf * 8 + (lane >> 2);
                    bf[nf][0] = Vs[buf * 8320 + kl * 260 + col];
                    bf[nf][1] = Vs[buf * 8320 + (kl + 4) * 260 + col];
                }
#pragma unroll
                for (int mf = 0; mf < 2; mf++)
#pragma unroll
                    for (int nf = 0; nf < 8; nf++)
                        mma8a(acc2[mf][nf], af[mf], bf[nf]);
            }
            if (kt < NF1 - 1) sts2(buf ^ 1);
            __syncthreads();
        }

#pragma unroll
        for (int mf = 0; mf < 2; mf++)
#pragma unroll
            for (int nf = 0; nf < 8; nf++)
#pragma unroll
                for (int r = 0; r < 4; r++) {
                    int row = wm * 32 + mf * 16 + (lane >> 2) + ((r & 2) ? 8 : 0);
                    int c = half * 256 + wn * 64 + nf * 8 + (lane & 3) * 2 + (r & 1);
                    int m = b * 8192 + (i0 + row) * 32 + s;
                    store_attn_packed(m, c, __uint_as_float(f2tf(acc2[mf][nf][r])));
                }
        __syncthreads();
    }
}

// ---------------------------------------------------------------------------
extern "C" void kernel_launch(void* const* d_in, const int* in_sizes, int n_in,
                              void* d_out, int out_size)
{
    const float* x  = (const float*)d_in[0];
    const float* Wq = (const float*)d_in[1];
    const float* bq = (const float*)d_in[2];
    const float* Wp = (const float*)d_in[3];
    const float* bp = (const float*)d_in[4];
    float* out = (float*)d_out;

    void *pxr, *pwq, *pwp, *pattn;
    cudaGetSymbolAddress(&pxr, g_xr);
    cudaGetSymbolAddress(&pwq, g_wq);
    cudaGetSymbolAddress(&pwp, g_wp);
    cudaGetSymbolAddress(&pattn, g_attn);

    const int smG = 3 * 32768;                                          // 98304
    const int smA128 = 64 * 132 * 4 + 2 * 32 * 260 * 4;                 // 100352
    const int smA192 = 64 * 196 * 4 + (2 * 64 * 36 + 2 * 192 * 36) * 4; // 123904

    cudaFuncSetAttribute(tc_gemm<0>, cudaFuncAttributeMaxDynamicSharedMemorySize, smG);
    cudaFuncSetAttribute(tc_gemm<1>, cudaFuncAttributeMaxDynamicSharedMemorySize, smG);
    cudaFuncSetAttribute(attn_kernel<128>, cudaFuncAttributeMaxDynamicSharedMemorySize, smA128);
    cudaFuncSetAttribute(attn_kernel<192>, cudaFuncAttributeMaxDynamicSharedMemorySize, smA192);

    // 0) pack + tf32-round operands into fragment order
    pack_x<<<32768, 256>>>(x, (uint4*)pxr);
    pack_w<1536><<<768, 256>>>(Wq, (uint4*)pwq);
    pack_w<512><<<256, 256>>>(Wp, (uint4*)pwp);

    // 1) QKV projection + head-split scatter into g_q/g_k/g_v
    tc_gemm<0><<<dim3(12, 512), 256, smG>>>((const uint4*)pxr, (const uint4*)pwq, bq, nullptr);

    // 2) banded attention (writes packed g_attn)
    attn_kernel<128><<<dim3(2, 256), 256, smA128>>>();
    attn_kernel<192><<<dim3(2, 256), 256, smA192>>>();

    // 3) output projection
    tc_gemm<1><<<dim3(4, 512), 256, smG>>>((const uint4*)pattn, (const uint4*)pwp, bp, out);
}